// round 5
// baseline (speedup 1.0000x reference)
#include <cuda_runtime.h>

#define HH    136
#define WWW   200
#define HW    (HH*WWW)
#define OH    272
#define OW    400
#define NIMG  8
#define NINST 512
#define NPAR  169
#define TB    128

typedef unsigned long long u64;

// scratch (device globals: allocation-free rule)
__device__ float g_part[NINST * 8 * 3];                   // per-(inst,band) partial sums

__constant__ float c_soi[6] = {64.f, 128.f, 256.f, 512.f, 1024.f, 2048.f};

// ---------- packed f32x2 helpers ----------
__device__ __forceinline__ u64 pk(float lo, float hi) {
    u64 r; asm("mov.b64 %0, {%1,%2};" : "=l"(r) : "f"(lo), "f"(hi)); return r;
}
__device__ __forceinline__ void upk(u64 v, float& lo, float& hi) {
    asm("mov.b64 {%0,%1}, %2;" : "=f"(lo), "=f"(hi) : "l"(v));
}
__device__ __forceinline__ u64 fma2(u64 a, u64 b, u64 c) {
    u64 d; asm("fma.rn.f32x2 %0, %1, %2, %3;" : "=l"(d) : "l"(a), "l"(b), "l"(c)); return d;
}
__device__ __forceinline__ u64 relu2(u64 v) {
    float lo, hi; upk(v, lo, hi);
    lo = fmaxf(lo, 0.f); hi = fmaxf(hi, 0.f);
    return pk(lo, hi);
}

// ---------- fused MLP + upsample + sigmoid + dice partials ----------
__global__ void __launch_bounds__(TB) mask_kernel(
    const float* __restrict__ mf,
    const float* __restrict__ params,
    const float* __restrict__ iloc,
    const float* __restrict__ gt,
    const int*   __restrict__ im_inds,
    const int*   __restrict__ fpn)
{
    const int b   = blockIdx.x;   // band 0..7 (17 input rows each)
    const int n   = blockIdx.y;   // instance
    const int tid = threadIdx.x;

    __shared__ float sw[NPAR];
    __shared__ float sl[18 * WWW];           // band logits
    __shared__ float red[3][TB / 32];

    for (int i = tid; i < NPAR; i += TB) sw[i] = params[n * NPAR + i];
    const int   im   = __ldg(&im_inds[n]);
    const float sinv = 1.f / c_soi[__ldg(&fpn[n])];
    const float locx = __ldg(&iloc[2 * n]);
    const float locy = __ldg(&iloc[2 * n + 1]);
    __syncthreads();

    const int r0      = b * 17;
    const int nrows   = min(18, HH - r0);    // 18, last band 17
    const int nchunks = nrows * 50;          // 4-px chunks per band
    const float* fimg = mf + (size_t)im * 8 * HW;

    // ---- phase 1: logits (4 pixels = 2 f32x2 packs per chunk) ----
    for (int g = tid; g < nchunks; g += TB) {
        const int row = g / 50;
        const int xb  = (g - row * 50) * 4;
        const int y   = r0 + row;
        const float* fb = fimg + y * WWW + xb;

        u64 acc[8][2];
#pragma unroll
        for (int o = 0; o < 8; o++) {
            u64 bb = pk(sw[152 + o], sw[152 + o]);
            acc[o][0] = bb; acc[o][1] = bb;
        }
        // channel 0: relx
        {
            u64 xc[2];
            xc[0] = pk((locx - (float)(8 * xb + 4))      * sinv,
                       (locx - (float)(8 * (xb+1) + 4))  * sinv);
            xc[1] = pk((locx - (float)(8 * (xb+2) + 4))  * sinv,
                       (locx - (float)(8 * (xb+3) + 4))  * sinv);
#pragma unroll
            for (int o = 0; o < 8; o++) {
                u64 w2 = pk(sw[o * 10], sw[o * 10]);
                acc[o][0] = fma2(w2, xc[0], acc[o][0]);
                acc[o][1] = fma2(w2, xc[1], acc[o][1]);
            }
        }
        // channel 1: rely (uniform over chunk)
        {
            float ry = (locy - (float)(8 * y + 4)) * sinv;
            u64 ryv = pk(ry, ry);
#pragma unroll
            for (int o = 0; o < 8; o++) {
                u64 w2 = pk(sw[o * 10 + 1], sw[o * 10 + 1]);
                acc[o][0] = fma2(w2, ryv, acc[o][0]);
                acc[o][1] = fma2(w2, ryv, acc[o][1]);
            }
        }
        // channels 2..9: feats (original [im][c][h][w] layout, L2-resident)
#pragma unroll
        for (int c = 0; c < 8; c++) {
            float4 v = *(const float4*)(fb + (size_t)c * HW);
            u64 xc0 = pk(v.x, v.y);
            u64 xc1 = pk(v.z, v.w);
#pragma unroll
            for (int o = 0; o < 8; o++) {
                u64 w2 = pk(sw[o * 10 + 2 + c], sw[o * 10 + 2 + c]);
                acc[o][0] = fma2(w2, xc0, acc[o][0]);
                acc[o][1] = fma2(w2, xc1, acc[o][1]);
            }
        }
        u64 h[8][2];
#pragma unroll
        for (int o = 0; o < 8; o++) {
            h[o][0] = relu2(acc[o][0]);
            h[o][1] = relu2(acc[o][1]);
        }

        // layer 2
        u64 a2[8][2];
#pragma unroll
        for (int o = 0; o < 8; o++) {
            u64 bb = pk(sw[160 + o], sw[160 + o]);
            a2[o][0] = bb; a2[o][1] = bb;
        }
#pragma unroll
        for (int c = 0; c < 8; c++) {
#pragma unroll
            for (int o = 0; o < 8; o++) {
                u64 w2 = pk(sw[80 + o * 8 + c], sw[80 + o * 8 + c]);
                a2[o][0] = fma2(w2, h[c][0], a2[o][0]);
                a2[o][1] = fma2(w2, h[c][1], a2[o][1]);
            }
        }
#pragma unroll
        for (int o = 0; o < 8; o++) {
            h[o][0] = relu2(a2[o][0]);
            h[o][1] = relu2(a2[o][1]);
        }

        // layer 3
        u64 o0, o1;
        {
            u64 bb = pk(sw[168], sw[168]);
            o0 = bb; o1 = bb;
        }
#pragma unroll
        for (int c = 0; c < 8; c++) {
            u64 w2 = pk(sw[144 + c], sw[144 + c]);
            o0 = fma2(w2, h[c][0], o0);
            o1 = fma2(w2, h[c][1], o1);
        }
        {
            float lo, hi;
            upk(o0, lo, hi);
            sl[row * WWW + xb]     = lo;
            sl[row * WWW + xb + 1] = hi;
            upk(o1, lo, hi);
            sl[row * WWW + xb + 2] = lo;
            sl[row * WWW + xb + 3] = hi;
        }
    }
    __syncthreads();

    // ---- phase 2: upsample + sigmoid + dice partials ----
    const int i_start = (r0 * 271 + 134) / 135;
    const int i_end   = (b == 7) ? OH : ((r0 + 17) * 271 + 134) / 135;
    const float* gtb  = gt + (size_t)n * OH * OW;

    float aI = 0.f, aS = 0.f, aT = 0.f;
    for (int i = i_start; i < i_end; i++) {
        const float fy = (float)i * (135.f / 271.f);
        const int   y0 = (int)fy;
        const float wy = fy - (float)y0;
        int ly0 = y0 - r0;
        int ly1 = min(y0 + 1, 135) - r0;
        ly0 = max(0, min(ly0, nrows - 1));
        ly1 = max(0, min(ly1, nrows - 1));
        const float* sl0 = &sl[ly0 * WWW];
        const float* sl1 = &sl[ly1 * WWW];
        const float* gtr = gtb + (size_t)i * OW;

        for (int j = tid; j < OW; j += TB) {
            float fx = (float)j * (199.f / 399.f);
            int   x0 = (int)fx;
            float wx = fx - (float)x0;
            int   x1 = min(x0 + 1, 199);

            float t00 = sl0[x0], t01 = sl0[x1];
            float t10 = sl1[x0], t11 = sl1[x1];
            float top = t00 + (t01 - t00) * wx;
            float bot = t10 + (t11 - t10) * wx;
            float v   = top + (bot - top) * wy;

            float s = __fdividef(1.f, 1.f + __expf(-v));
            float t = __ldg(&gtr[j]);

            aI = fmaf(s, t, aI);
            aS = fmaf(s, s, aS);
            aT += t;                 // t ∈ {0,1} so t*t == t
        }
    }

#pragma unroll
    for (int off = 16; off > 0; off >>= 1) {
        aI += __shfl_down_sync(0xffffffffu, aI, off);
        aS += __shfl_down_sync(0xffffffffu, aS, off);
        aT += __shfl_down_sync(0xffffffffu, aT, off);
    }
    const int wid = tid >> 5, lane = tid & 31;
    if (lane == 0) { red[0][wid] = aI; red[1][wid] = aS; red[2][wid] = aT; }
    __syncthreads();
    if (tid == 0) {
        float I = 0.f, S = 0.f, T = 0.f;
#pragma unroll
        for (int w = 0; w < TB / 32; w++) { I += red[0][w]; S += red[1][w]; T += red[2][w]; }
        float* gp = &g_part[(n * 8 + b) * 3];
        gp[0] = I; gp[1] = S; gp[2] = T;
    }
}

// ---------- finalize dice loss ----------
__global__ void finalize_kernel(float* __restrict__ out) {
    int n = blockIdx.x * blockDim.x + threadIdx.x;
    if (n >= NINST) return;
    float I = 0.f, S = 0.f, T = 0.f;
#pragma unroll
    for (int b = 0; b < 8; b++) {
        const float* gp = &g_part[(n * 8 + b) * 3];
        I += gp[0]; S += gp[1]; T += gp[2];
    }
    out[n] = 1.f - 2.f * I / (S + T + 1e-5f);
}

extern "C" void kernel_launch(void* const* d_in, const int* in_sizes, int n_in,
                              void* d_out, int out_size) {
    const float* mf     = (const float*)d_in[0];
    const float* params = (const float*)d_in[1];
    const float* iloc   = (const float*)d_in[2];
    const float* gt     = (const float*)d_in[3];
    const int*   imi    = (const int*)d_in[4];
    const int*   fpn    = (const int*)d_in[5];
    float*       out    = (float*)d_out;

    dim3 grid(8, NINST);
    mask_kernel<<<grid, TB>>>(mf, params, iloc, gt, imi, fpn);
    finalize_kernel<<<1, NINST>>>(out);
}